// round 16
// baseline (speedup 1.0000x reference)
#include <cuda_runtime.h>
#include <cuda_fp16.h>
#include <math.h>
#include <stdint.h>

// ============================================================================
// EdgeDecoder, HMMA m16n8k16 fp16 single-term (fp32 accum).
// Round 16: R15 + two sequential 64-edge sub-tiles per CTA (prologue amortized,
// sub-tile-1 weight chunks prefetched during sub-tile-0 epilogue).
// 128 thr, 4 CTAs/SM.
// ============================================================================

#define NTH 128

// packed fp16 weights, fragment order:
// [type][ks][ntpair8][lane32][w4]; Wbi K-permuted within 16-blocks
// (mem k = ks*16 + 4t + 2r + d holds logical k = ks*16 + 2t + 8r + d).
__device__ __align__(128) uint32_t g_wbi_pack[32768];   // 2 x 16ks x 8 x 32 x 4
__device__ __align__(128) uint32_t g_w1_pack[16384];    // 2 x 8ks  x 8 x 32 x 4

// ---- SMEM layout (bytes) ----
constexpr int OFF_A    = 0;        // A frags [mt4][slot8]*512 = 16384 (A2 aliases)
constexpr int OFF_RING = 16384;    // 2 x 16384 weight chunk ring
constexpr int OFF_W2   = 49152;    // f32[128]
constexpr int OFF_PART = 49664;    // f32[128]
constexpr int OFF_BBH2 = 50176;    // half2[64]
constexpr int OFF_B1H2 = 50304;    // half2[64]
constexpr int SMEM_TOTAL = 50688;

#define CPA(dst, src) \
    asm volatile("cp.async.cg.shared.global [%0], [%1], 16;" :: "r"(dst), "l"(src))
#define CPA_COMMIT() asm volatile("cp.async.commit_group;" ::: "memory")
#define CPA_WAIT(n)  asm volatile("cp.async.wait_group %0;" :: "n"(n) : "memory")

__device__ __forceinline__ uint32_t smem_to_u32(const void* p) {
    uint32_t a;
    asm("{ .reg .u64 t; cvta.to.shared.u64 t, %1; cvt.u32.u64 %0, t; }" : "=r"(a) : "l"(p));
    return a;
}

__device__ __forceinline__ void mma_f16(float c[4], const uint32_t a[4],
                                        uint32_t b0, uint32_t b1) {
    asm volatile(
        "mma.sync.aligned.m16n8k16.row.col.f32.f16.f16.f32 "
        "{%0,%1,%2,%3}, {%4,%5,%6,%7}, {%8,%9}, {%0,%1,%2,%3};"
        : "+f"(c[0]), "+f"(c[1]), "+f"(c[2]), "+f"(c[3])
        : "r"(a[0]), "r"(a[1]), "r"(a[2]), "r"(a[3]), "r"(b0), "r"(b1));
}

__device__ __forceinline__ uint32_t pack_h2(float a, float b) {
    __half2 h = __floats2half2_rn(a, b);
    return *(uint32_t*)&h;
}

// ELU on a half2 pair: elu(v) = max(v,0) + (exp(min(v,0)) - 1)
__device__ __forceinline__ __half2 elu2(__half2 v) {
    const __half2 z   = __float2half2_rn(0.f);
    const __half2 one = __float2half2_rn(1.f);
    __half2 vn = __hmin2(v, z);
    __half2 vp = __hmax2(v, z);
    return __hadd2(vp, __hsub2(h2exp(vn), one));
}
__device__ __forceinline__ uint32_t h2u(__half2 h) { return *(uint32_t*)&h; }

// ============================================================================
// Pre-pack: fp32 weights -> fp16 frag-order lines (Wbi K-permuted, W1 standard)
// ============================================================================
__global__ void pack_weights_kernel(
    const float* __restrict__ Wbi_ui, const float* __restrict__ W1_ui,
    const float* __restrict__ Wbi_iu, const float* __restrict__ W1_iu)
{
    int id = blockIdx.x * blockDim.x + threadIdx.x;
    if (id < 32768) {
        int w = id & 3, lane = (id >> 2) & 31, ntp = (id >> 7) & 7;
        int ks = (id >> 10) & 15;
        int type = (id >> 14) & 1;
        const float* W = type ? Wbi_iu : Wbi_ui;
        int nt = ntp * 2 + (w >> 1), r = w & 1;
        int k = ks * 16 + (lane & 3) * 4 + r * 2;      // permuted-K
        int n = nt * 8 + (lane >> 2);
        g_wbi_pack[id] = pack_h2(W[k * 128 + n], W[(k + 1) * 128 + n]);
    } else {
        int id2 = id - 32768;
        if (id2 >= 16384) return;
        int w = id2 & 3, lane = (id2 >> 2) & 31, ntp = (id2 >> 7) & 7;
        int ks = (id2 >> 10) & 7;
        int type = (id2 >> 13) & 1;
        const float* W = type ? W1_iu : W1_ui;
        int nt = ntp * 2 + (w >> 1), r = w & 1;
        int k = ks * 16 + (lane & 3) * 2 + r * 8;      // standard
        int n = nt * 8 + (lane >> 2);
        g_w1_pack[id2] = pack_h2(W[k * 128 + n], W[(k + 1) * 128 + n]);
    }
}

// one ks step for one warp: 2 A LDS.128 + 4 B LDS.128 + 16 HMMA
// A buffer: [mt4][slot8]*512.
__device__ __forceinline__ void mma_step(
    const char* smA, const char* smB_ks, int slotA, int mi, int ni, int l16,
    float C[2][8][4])
{
    uint4 A0 = *(const uint4*)(smA + ((mi * 2 + 0) * 8 + slotA) * 512 + l16);
    uint4 A1 = *(const uint4*)(smA + ((mi * 2 + 1) * 8 + slotA) * 512 + l16);
    #pragma unroll
    for (int p = 0; p < 4; p++) {
        uint4 B = *(const uint4*)(smB_ks + (ni * 4 + p) * 512 + l16);
        mma_f16(C[0][2 * p],     &A0.x, B.x, B.y);
        mma_f16(C[1][2 * p],     &A1.x, B.x, B.y);
        mma_f16(C[0][2 * p + 1], &A0.x, B.z, B.w);
        mma_f16(C[1][2 * p + 1], &A1.x, B.z, B.w);
    }
}

// chunk c: 4 ks of B lines (16 KB). c<4 -> Wbi ks 4c..4c+3; c>=4 -> W1.
__device__ __forceinline__ void issue_chunk(
    uint32_t ring_u32, int c, const uint32_t* wbiP, const uint32_t* w1P, int tid)
{
    const uint32_t* src = (c < 4) ? (wbiP + c * 4096) : (w1P + (c - 4) * 4096);
    uint32_t dst = ring_u32 + (uint32_t)(c & 1) * 16384;
    #pragma unroll
    for (int q = 0; q < 8; q++)
        CPA(dst + (uint32_t)(tid + q * 128) * 16, src + (tid + q * 128) * 4);
    CPA_COMMIT();
}

// issue 4-slot gather group: 8 LDG.128 parked in registers
__device__ __forceinline__ void ldg_grp(
    float4 pk[4][2], const float* eb, uint32_t o0, uint32_t o1, int ksbase, int t)
{
    #pragma unroll
    for (int j = 0; j < 4; j++) {
        const int kf = (ksbase + j) * 16 + 4 * t;
        pk[j][0] = *(const float4*)(eb + o0 + kf);
        pk[j][1] = *(const float4*)(eb + o1 + kf);
    }
}
// drain parked group into A slots [slotbase..slotbase+3]
__device__ __forceinline__ void sts_grp(
    const float4 pk[4][2], char* smA, int slotbase, int wid, int l16)
{
    #pragma unroll
    for (int j = 0; j < 4; j++) {
        uint4 hi;
        hi.x = pack_h2(pk[j][0].x, pk[j][0].y);
        hi.y = pack_h2(pk[j][1].x, pk[j][1].y);
        hi.z = pack_h2(pk[j][0].z, pk[j][0].w);
        hi.w = pack_h2(pk[j][1].z, pk[j][1].w);
        *(uint4*)(smA + (wid * 8 + slotbase + j) * 512 + l16) = hi;
    }
}

__global__ __launch_bounds__(NTH, 4)
void edge_decoder_mma(
    const float* __restrict__ user_emb, const float* __restrict__ item_emb,
    const void* __restrict__ ei_ui, const void* __restrict__ ei_iu,
    const float* __restrict__ bbi_ui, const float* __restrict__ b1_ui,
    const float* __restrict__ W2_ui,  const float* __restrict__ b2_ui,
    const float* __restrict__ bbi_iu, const float* __restrict__ b1_iu,
    const float* __restrict__ W2_iu,  const float* __restrict__ b2_iu,
    float* __restrict__ out, int E)
{
    extern __shared__ char sm[];
    const uint32_t sm_u32 = smem_to_u32(sm);
    const int tid  = threadIdx.x;
    const int wid  = tid >> 5;          // 0..3
    const int lane = tid & 31;
    const int mi   = wid & 1;           // 32-row group (2 m16 tiles)
    const int ni   = wid >> 1;          // 64-col group (0..1)
    const int g    = lane >> 2;
    const int t    = lane & 3;
    const int l16  = lane * 16;

    const int type  = blockIdx.y;
    const int base0 = blockIdx.x * 128; // two 64-edge sub-tiles

    const float* srcE = type ? item_emb : user_emb;
    const float* dstE = type ? user_emb : item_emb;
    const void*  ei   = type ? ei_iu : ei_ui;
    const float* bbi  = type ? bbi_iu : bbi_ui;
    const float* b1   = type ? b1_iu : b1_ui;
    const float* W2   = type ? W2_iu : W2_ui;
    const float* b2   = type ? b2_iu : b2_ui;
    const uint32_t* wbiP = g_wbi_pack + (size_t)type * 16384;
    const uint32_t* w1P  = g_w1_pack  + (size_t)type * 8192;

    float*    sW2   = (float*)(sm + OFF_W2);
    float2*   sW2f2 = (float2*)(sm + OFF_W2);
    float*    sPart = (float*)(sm + OFF_PART);
    __half2*  sBbiH = (__half2*)(sm + OFF_BBH2);
    __half2*  sB1H  = (__half2*)(sm + OFF_B1H2);
    char*     smA   = sm + OFF_A;
    char*     smRing = sm + OFF_RING;

    // start weight stream immediately (chunks 0,1 of sub-tile 0)
    issue_chunk(sm_u32 + OFF_RING, 0, wbiP, w1P, tid);
    issue_chunk(sm_u32 + OFF_RING, 1, wbiP, w1P, tid);

    // int64-index detection (broadcast L2 reads)
    bool is64;
    {
        const int* w = (const int*)ei_ui;
        int all0 = 1;
        #pragma unroll
        for (int k = 0; k < 8; k++) all0 &= (w[2 * k + 1] == 0);
        is64 = (all0 != 0);
    }
    const float b2v = b2[0];

    // ---- direct per-warp index loads for BOTH sub-tiles ----
    const int m0 = wid * 16 + g;
    uint32_t so0[2], so1[2], do0[2], do1[2];
    #pragma unroll
    for (int st = 0; st < 2; st++) {
        const int ge0 = base0 + st * 64 + m0, ge1 = ge0 + 8;
        long long i0 = 0, i1 = 0, i2 = 0, i3 = 0;
        if (is64) {
            const long long* e64 = (const long long*)ei;
            if (ge0 < E) { i0 = e64[ge0]; i2 = e64[E + ge0]; }
            if (ge1 < E) { i1 = e64[ge1]; i3 = e64[E + ge1]; }
        } else {
            const int* e32 = (const int*)ei;
            if (ge0 < E) { i0 = e32[ge0]; i2 = e32[E + ge0]; }
            if (ge1 < E) { i1 = e32[ge1]; i3 = e32[E + ge1]; }
        }
        so0[st] = (uint32_t)i0 << 7; so1[st] = (uint32_t)i1 << 7;
        do0[st] = (uint32_t)i2 << 7; do1[st] = (uint32_t)i3 << 7;
    }

    // bias tables (visibility covered by chunk-0 barrier below)
    if (tid < 64) {
        sBbiH[tid] = __floats2half2_rn(bbi[2 * tid], bbi[2 * tid + 1]);
        sB1H[tid]  = __floats2half2_rn(b1[2 * tid],  b1[2 * tid + 1]);
    }
    sW2[tid] = W2[tid];

    #pragma unroll
    for (int st = 0; st < 2; st++) {
        const int base = base0 + st * 64;

        float C[2][8][4];
        #pragma unroll
        for (int m = 0; m < 2; m++)
            #pragma unroll
            for (int a = 0; a < 8; a++)
                #pragma unroll
                for (int b = 0; b < 4; b++) C[m][a][b] = 0.f;

        float4 pk[4][2];

        // ---- pipelined gather + GEMM1 (4 chunks x 4 ks) ----
        ldg_grp(pk, srcE, so0[st], so1[st], 0, t);     // src ks0-3
        sts_grp(pk, smA, 0, wid, l16);                 // exposed wait
        ldg_grp(pk, srcE, so0[st], so1[st], 4, t);     // park src ks4-7

        // chunk 0: B ks0-3, A slots 0-3
        CPA_WAIT(1);
        __syncthreads();                               // chunk0 + A grp0 (+biases) visible
        #pragma unroll
        for (int klc = 0; klc < 4; klc++)
            mma_step(smA, smRing + klc * 4096, klc, mi, ni, l16, C);
        __syncthreads();
        issue_chunk(sm_u32 + OFF_RING, 2, wbiP, w1P, tid);
        sts_grp(pk, smA, 4, wid, l16);                 // drain grp1
        ldg_grp(pk, dstE, do0[st], do1[st], 0, t);     // park dst ks0-3

        // chunk 1: B ks4-7, A slots 4-7
        CPA_WAIT(1);
        __syncthreads();
        #pragma unroll
        for (int klc = 0; klc < 4; klc++)
            mma_step(smA, smRing + 16384 + klc * 4096, 4 + klc, mi, ni, l16, C);
        __syncthreads();
        issue_chunk(sm_u32 + OFF_RING, 3, wbiP, w1P, tid);
        sts_grp(pk, smA, 0, wid, l16);                 // drain dst grp
        ldg_grp(pk, dstE, do0[st], do1[st], 4, t);     // park dst ks4-7

        // chunk 2: B ks8-11, A slots 0-3 (dst)
        CPA_WAIT(1);
        __syncthreads();
        #pragma unroll
        for (int klc = 0; klc < 4; klc++)
            mma_step(smA, smRing + klc * 4096, klc, mi, ni, l16, C);
        __syncthreads();
        issue_chunk(sm_u32 + OFF_RING, 4, wbiP, w1P, tid);
        sts_grp(pk, smA, 4, wid, l16);                 // drain dst grp2

        // chunk 3: B ks12-15, A slots 4-7 (dst)
        CPA_WAIT(1);
        __syncthreads();
        #pragma unroll
        for (int klc = 0; klc < 4; klc++)
            mma_step(smA, smRing + 16384 + klc * 4096, 4 + klc, mi, ni, l16, C);
        __syncthreads();
        issue_chunk(sm_u32 + OFF_RING, 5, wbiP, w1P, tid);

        // ---- epilogue1 (half2): elu2(h2(C)+bias) -> A2 slots (ks2 = ni*4+s) ----
        #pragma unroll
        for (int s = 0; s < 4; s++) {
            const int hb = ni * 32 + s * 8 + t;
            const __half2 bb0 = sBbiH[hb];
            const __half2 bb1 = sBbiH[hb + 4];
            #pragma unroll
            for (int mtl = 0; mtl < 2; mtl++) {
                uint4 hi;
                hi.x = h2u(elu2(__hadd2(__floats2half2_rn(C[mtl][2*s][0],   C[mtl][2*s][1]),   bb0)));
                hi.y = h2u(elu2(__hadd2(__floats2half2_rn(C[mtl][2*s][2],   C[mtl][2*s][3]),   bb0)));
                hi.z = h2u(elu2(__hadd2(__floats2half2_rn(C[mtl][2*s+1][0], C[mtl][2*s+1][1]), bb1)));
                hi.w = h2u(elu2(__hadd2(__floats2half2_rn(C[mtl][2*s+1][2], C[mtl][2*s+1][3]), bb1)));
                const int mt2 = mi * 2 + mtl, ks2 = ni * 4 + s;
                *(uint4*)(smA + (mt2 * 8 + ks2) * 512 + l16) = hi;
            }
        }

        // ---- GEMM2: chunks 4,5 (W1), local ks 0..7; C reused ----
        #pragma unroll
        for (int m = 0; m < 2; m++)
            #pragma unroll
            for (int a = 0; a < 8; a++)
                #pragma unroll
                for (int b = 0; b < 4; b++) C[m][a][b] = 0.f;

        CPA_WAIT(1);
        __syncthreads();                               // chunk 4 + A2 visible
        #pragma unroll
        for (int klc = 0; klc < 4; klc++)
            mma_step(smA, smRing + klc * 4096, klc, mi, ni, l16, C);
        CPA_WAIT(0);
        __syncthreads();                               // chunk 5 visible; buf0 reads done
        if (st == 0)                                   // prefetch next sub-tile chunk 0
            issue_chunk(sm_u32 + OFF_RING, 0, wbiP, w1P, tid);
        #pragma unroll
        for (int klc = 0; klc < 4; klc++)
            mma_step(smA, smRing + 16384 + klc * 4096, 4 + klc, mi, ni, l16, C);

        // ---- epilogue2 (half2 elu, fp32 dot): ELU(C+b1).W2, quad reduce ----
        float r0[2] = {0.f, 0.f}, r1[2] = {0.f, 0.f};
        #pragma unroll
        for (int ntl = 0; ntl < 8; ntl++) {
            const int hb = ni * 32 + ntl * 4 + t;
            const __half2 b = sB1H[hb];
            const float2  w = sW2f2[hb];
            #pragma unroll
            for (int mtl = 0; mtl < 2; mtl++) {
                __half2 h01 = elu2(__hadd2(__floats2half2_rn(C[mtl][ntl][0], C[mtl][ntl][1]), b));
                __half2 h23 = elu2(__hadd2(__floats2half2_rn(C[mtl][ntl][2], C[mtl][ntl][3]), b));
                float2 f01 = __half22float2(h01);
                float2 f23 = __half22float2(h23);
                r0[mtl] += f01.x * w.x + f01.y * w.y;
                r1[mtl] += f23.x * w.x + f23.y * w.y;
            }
        }
        #pragma unroll
        for (int mtl = 0; mtl < 2; mtl++) {
            r0[mtl] += __shfl_xor_sync(0xffffffffu, r0[mtl], 1);
            r1[mtl] += __shfl_xor_sync(0xffffffffu, r1[mtl], 1);
            r0[mtl] += __shfl_xor_sync(0xffffffffu, r0[mtl], 2);
            r1[mtl] += __shfl_xor_sync(0xffffffffu, r1[mtl], 2);
            if (t == 0) {
                const int m = (mi * 2 + mtl) * 16 + g;
                sPart[ni * 64 + m]     = r0[mtl];
                sPart[ni * 64 + m + 8] = r1[mtl];
            }
        }
        __syncthreads();                               // sPart ready; GEMM2/A reads done
        if (tid < 64) {
            const int ge = base + tid;
            if (ge < E) {
                float s = sPart[tid] + sPart[64 + tid] + b2v;
                out[(size_t)type * E + ge] = 1.f / (1.f + __expf(-s));
            }
        }
        if (st == 0)                                   // prefetch next sub-tile chunk 1
            issue_chunk(sm_u32 + OFF_RING, 1, wbiP, w1P, tid);
        // next sub-tile's chunk-0 CPA_WAIT+barrier orders A/sPart reuse
    }
}

extern "C" void kernel_launch(void* const* d_in, const int* in_sizes, int n_in,
                              void* d_out, int out_size) {
    (void)n_in; (void)out_size;
    const int E = in_sizes[2] / 2;
    pack_weights_kernel<<<96, 512>>>(
        (const float*)d_in[4], (const float*)d_in[6],
        (const float*)d_in[10], (const float*)d_in[12]);
    cudaFuncSetAttribute(edge_decoder_mma,
                         cudaFuncAttributeMaxDynamicSharedMemorySize, SMEM_TOTAL);
    dim3 grid((E + 127) / 128, 2);
    edge_decoder_mma<<<grid, NTH, SMEM_TOTAL>>>(
        (const float*)d_in[0],  (const float*)d_in[1],
        d_in[2], d_in[3],
        (const float*)d_in[5],  (const float*)d_in[7],
        (const float*)d_in[8],  (const float*)d_in[9],
        (const float*)d_in[11], (const float*)d_in[13],
        (const float*)d_in[14], (const float*)d_in[15],
        (float*)d_out, E);
}

// round 17
// speedup vs baseline: 1.1287x; 1.1287x over previous
#include <cuda_runtime.h>
#include <cuda_fp16.h>
#include <math.h>
#include <stdint.h>

// ============================================================================
// EdgeDecoder, HMMA m16n8k16 fp16 single-term (fp32 accum).
// Round 17: R15 + barrier dieting (11 -> 8 bars/tile): ring-overwrite ordering
// folded into the next chunk's WAIT barrier. 64-edge tiles, 128 thr, 4 CTAs/SM.
// ============================================================================

#define NTH 128

// packed fp16 weights, fragment order:
// [type][ks][ntpair8][lane32][w4]; Wbi K-permuted within 16-blocks
// (mem k = ks*16 + 4t + 2r + d holds logical k = ks*16 + 2t + 8r + d).
__device__ __align__(128) uint32_t g_wbi_pack[32768];   // 2 x 16ks x 8 x 32 x 4
__device__ __align__(128) uint32_t g_w1_pack[16384];    // 2 x 8ks  x 8 x 32 x 4

// ---- SMEM layout (bytes) ----
constexpr int OFF_A    = 0;        // A frags [mt4][slot8]*512 = 16384 (A2 aliases)
constexpr int OFF_RING = 16384;    // 2 x 16384 weight chunk ring
constexpr int OFF_W2   = 49152;    // f32[128]
constexpr int OFF_PART = 49664;    // f32[128]
constexpr int OFF_BBH2 = 50176;    // half2[64]
constexpr int OFF_B1H2 = 50304;    // half2[64]
constexpr int SMEM_TOTAL = 50688;

#define CPA(dst, src) \
    asm volatile("cp.async.cg.shared.global [%0], [%1], 16;" :: "r"(dst), "l"(src))
#define CPA_COMMIT() asm volatile("cp.async.commit_group;" ::: "memory")
#define CPA_WAIT(n)  asm volatile("cp.async.wait_group %0;" :: "n"(n) : "memory")

__device__ __forceinline__ uint32_t smem_to_u32(const void* p) {
    uint32_t a;
    asm("{ .reg .u64 t; cvta.to.shared.u64 t, %1; cvt.u32.u64 %0, t; }" : "=r"(a) : "l"(p));
    return a;
}

__device__ __forceinline__ void mma_f16(float c[4], const uint32_t a[4],
                                        uint32_t b0, uint32_t b1) {
    asm volatile(
        "mma.sync.aligned.m16n8k16.row.col.f32.f16.f16.f32 "
        "{%0,%1,%2,%3}, {%4,%5,%6,%7}, {%8,%9}, {%0,%1,%2,%3};"
        : "+f"(c[0]), "+f"(c[1]), "+f"(c[2]), "+f"(c[3])
        : "r"(a[0]), "r"(a[1]), "r"(a[2]), "r"(a[3]), "r"(b0), "r"(b1));
}

__device__ __forceinline__ uint32_t pack_h2(float a, float b) {
    __half2 h = __floats2half2_rn(a, b);
    return *(uint32_t*)&h;
}

// ELU on a half2 pair: elu(v) = max(v,0) + (exp(min(v,0)) - 1)
__device__ __forceinline__ __half2 elu2(__half2 v) {
    const __half2 z   = __float2half2_rn(0.f);
    const __half2 one = __float2half2_rn(1.f);
    __half2 vn = __hmin2(v, z);
    __half2 vp = __hmax2(v, z);
    return __hadd2(vp, __hsub2(h2exp(vn), one));
}
__device__ __forceinline__ uint32_t h2u(__half2 h) { return *(uint32_t*)&h; }

// ============================================================================
// Pre-pack: fp32 weights -> fp16 frag-order lines (Wbi K-permuted, W1 standard)
// ============================================================================
__global__ void pack_weights_kernel(
    const float* __restrict__ Wbi_ui, const float* __restrict__ W1_ui,
    const float* __restrict__ Wbi_iu, const float* __restrict__ W1_iu)
{
    int id = blockIdx.x * blockDim.x + threadIdx.x;
    if (id < 32768) {
        int w = id & 3, lane = (id >> 2) & 31, ntp = (id >> 7) & 7;
        int ks = (id >> 10) & 15;
        int type = (id >> 14) & 1;
        const float* W = type ? Wbi_iu : Wbi_ui;
        int nt = ntp * 2 + (w >> 1), r = w & 1;
        int k = ks * 16 + (lane & 3) * 4 + r * 2;      // permuted-K
        int n = nt * 8 + (lane >> 2);
        g_wbi_pack[id] = pack_h2(W[k * 128 + n], W[(k + 1) * 128 + n]);
    } else {
        int id2 = id - 32768;
        if (id2 >= 16384) return;
        int w = id2 & 3, lane = (id2 >> 2) & 31, ntp = (id2 >> 7) & 7;
        int ks = (id2 >> 10) & 7;
        int type = (id2 >> 13) & 1;
        const float* W = type ? W1_iu : W1_ui;
        int nt = ntp * 2 + (w >> 1), r = w & 1;
        int k = ks * 16 + (lane & 3) * 2 + r * 8;      // standard
        int n = nt * 8 + (lane >> 2);
        g_w1_pack[id2] = pack_h2(W[k * 128 + n], W[(k + 1) * 128 + n]);
    }
}

// one ks step for one warp: 2 A LDS.128 + 4 B LDS.128 + 16 HMMA
// A buffer: [mt4][slot8]*512.
__device__ __forceinline__ void mma_step(
    const char* smA, const char* smB_ks, int slotA, int mi, int ni, int l16,
    float C[2][8][4])
{
    uint4 A0 = *(const uint4*)(smA + ((mi * 2 + 0) * 8 + slotA) * 512 + l16);
    uint4 A1 = *(const uint4*)(smA + ((mi * 2 + 1) * 8 + slotA) * 512 + l16);
    #pragma unroll
    for (int p = 0; p < 4; p++) {
        uint4 B = *(const uint4*)(smB_ks + (ni * 4 + p) * 512 + l16);
        mma_f16(C[0][2 * p],     &A0.x, B.x, B.y);
        mma_f16(C[1][2 * p],     &A1.x, B.x, B.y);
        mma_f16(C[0][2 * p + 1], &A0.x, B.z, B.w);
        mma_f16(C[1][2 * p + 1], &A1.x, B.z, B.w);
    }
}

// chunk c: 4 ks of B lines (16 KB). c<4 -> Wbi ks 4c..4c+3; c>=4 -> W1.
__device__ __forceinline__ void issue_chunk(
    uint32_t ring_u32, int c, const uint32_t* wbiP, const uint32_t* w1P, int tid)
{
    const uint32_t* src = (c < 4) ? (wbiP + c * 4096) : (w1P + (c - 4) * 4096);
    uint32_t dst = ring_u32 + (uint32_t)(c & 1) * 16384;
    #pragma unroll
    for (int q = 0; q < 8; q++)
        CPA(dst + (uint32_t)(tid + q * 128) * 16, src + (tid + q * 128) * 4);
    CPA_COMMIT();
}

// issue 4-slot gather group: 8 LDG.128 parked in registers
__device__ __forceinline__ void ldg_grp(
    float4 pk[4][2], const float* eb, uint32_t o0, uint32_t o1, int ksbase, int t)
{
    #pragma unroll
    for (int j = 0; j < 4; j++) {
        const int kf = (ksbase + j) * 16 + 4 * t;
        pk[j][0] = *(const float4*)(eb + o0 + kf);
        pk[j][1] = *(const float4*)(eb + o1 + kf);
    }
}
// drain parked group into A slots [slotbase..slotbase+3]
__device__ __forceinline__ void sts_grp(
    const float4 pk[4][2], char* smA, int slotbase, int wid, int l16)
{
    #pragma unroll
    for (int j = 0; j < 4; j++) {
        uint4 hi;
        hi.x = pack_h2(pk[j][0].x, pk[j][0].y);
        hi.y = pack_h2(pk[j][1].x, pk[j][1].y);
        hi.z = pack_h2(pk[j][0].z, pk[j][0].w);
        hi.w = pack_h2(pk[j][1].z, pk[j][1].w);
        *(uint4*)(smA + (wid * 8 + slotbase + j) * 512 + l16) = hi;
    }
}

__global__ __launch_bounds__(NTH, 4)
void edge_decoder_mma(
    const float* __restrict__ user_emb, const float* __restrict__ item_emb,
    const void* __restrict__ ei_ui, const void* __restrict__ ei_iu,
    const float* __restrict__ bbi_ui, const float* __restrict__ b1_ui,
    const float* __restrict__ W2_ui,  const float* __restrict__ b2_ui,
    const float* __restrict__ bbi_iu, const float* __restrict__ b1_iu,
    const float* __restrict__ W2_iu,  const float* __restrict__ b2_iu,
    float* __restrict__ out, int E)
{
    extern __shared__ char sm[];
    const uint32_t sm_u32 = smem_to_u32(sm);
    const int tid  = threadIdx.x;
    const int wid  = tid >> 5;          // 0..3
    const int lane = tid & 31;
    const int mi   = wid & 1;           // 32-row group (2 m16 tiles)
    const int ni   = wid >> 1;          // 64-col group (0..1)
    const int g    = lane >> 2;
    const int t    = lane & 3;
    const int l16  = lane * 16;

    const int type = blockIdx.y;
    const int base = blockIdx.x * 64;

    const float* srcE = type ? item_emb : user_emb;
    const float* dstE = type ? user_emb : item_emb;
    const void*  ei   = type ? ei_iu : ei_ui;
    const float* bbi  = type ? bbi_iu : bbi_ui;
    const float* b1   = type ? b1_iu : b1_ui;
    const float* W2   = type ? W2_iu : W2_ui;
    const float* b2   = type ? b2_iu : b2_ui;
    const uint32_t* wbiP = g_wbi_pack + (size_t)type * 16384;
    const uint32_t* w1P  = g_w1_pack  + (size_t)type * 8192;

    float*    sW2   = (float*)(sm + OFF_W2);
    float2*   sW2f2 = (float2*)(sm + OFF_W2);
    float*    sPart = (float*)(sm + OFF_PART);
    __half2*  sBbiH = (__half2*)(sm + OFF_BBH2);
    __half2*  sB1H  = (__half2*)(sm + OFF_B1H2);
    char*     smA   = sm + OFF_A;
    char*     smRing = sm + OFF_RING;

    // start weight stream immediately (chunks 0,1)
    issue_chunk(sm_u32 + OFF_RING, 0, wbiP, w1P, tid);
    issue_chunk(sm_u32 + OFF_RING, 1, wbiP, w1P, tid);

    // int64-index detection (broadcast L2 reads)
    bool is64;
    {
        const int* w = (const int*)ei_ui;
        int all0 = 1;
        #pragma unroll
        for (int k = 0; k < 8; k++) all0 &= (w[2 * k + 1] == 0);
        is64 = (all0 != 0);
    }
    const float b2v = b2[0];

    // ---- direct per-warp index loads (quad-redundant -> L2 broadcast) ----
    const int m0 = wid * 16 + g;
    uint32_t so0, so1, do0, do1;
    {
        const int ge0 = base + m0, ge1 = base + m0 + 8;
        long long i0 = 0, i1 = 0, i2 = 0, i3 = 0;
        if (is64) {
            const long long* e64 = (const long long*)ei;
            if (ge0 < E) { i0 = e64[ge0]; i2 = e64[E + ge0]; }
            if (ge1 < E) { i1 = e64[ge1]; i3 = e64[E + ge1]; }
        } else {
            const int* e32 = (const int*)ei;
            if (ge0 < E) { i0 = e32[ge0]; i2 = e32[E + ge0]; }
            if (ge1 < E) { i1 = e32[ge1]; i3 = e32[E + ge1]; }
        }
        so0 = (uint32_t)i0 << 7; so1 = (uint32_t)i1 << 7;
        do0 = (uint32_t)i2 << 7; do1 = (uint32_t)i3 << 7;
    }

    // bias tables (visibility covered by B1 below)
    if (tid < 64) {
        sBbiH[tid] = __floats2half2_rn(bbi[2 * tid], bbi[2 * tid + 1]);
        sB1H[tid]  = __floats2half2_rn(b1[2 * tid],  b1[2 * tid + 1]);
    }
    sW2[tid] = W2[tid];

    float C[2][8][4];
    #pragma unroll
    for (int m = 0; m < 2; m++)
        #pragma unroll
        for (int a = 0; a < 8; a++)
            #pragma unroll
            for (int b = 0; b < 4; b++) C[m][a][b] = 0.f;

    float4 pk[4][2];

    // ---- pipelined gather + GEMM1 (4 chunks x 4 ks), 1 bar per chunk ----
    ldg_grp(pk, srcE, so0, so1, 0, t);                 // src ks0-3
    sts_grp(pk, smA, 0, wid, l16);                     // exposed wait (once)
    ldg_grp(pk, srcE, so0, so1, 4, t);                 // park src ks4-7

    // B1: chunk0 + A slots0-3 + biases visible
    CPA_WAIT(1);
    __syncthreads();
    #pragma unroll
    for (int klc = 0; klc < 4; klc++)
        mma_step(smA, smRing + klc * 4096, klc, mi, ni, l16, C);
    sts_grp(pk, smA, 4, wid, l16);                     // drain src grp1
    ldg_grp(pk, dstE, do0, do1, 0, t);                 // park dst ks0-3

    // B2: chunk1 done; all buf0 reads done; slots4-7 visible
    CPA_WAIT(0);
    __syncthreads();
    issue_chunk(sm_u32 + OFF_RING, 2, wbiP, w1P, tid); // buf0 (safe post-B2)
    #pragma unroll
    for (int klc = 0; klc < 4; klc++)
        mma_step(smA, smRing + 16384 + klc * 4096, 4 + klc, mi, ni, l16, C);
    sts_grp(pk, smA, 0, wid, l16);                     // drain dst grp0
    ldg_grp(pk, dstE, do0, do1, 4, t);                 // park dst ks4-7

    // B3: chunk2 done; buf1 reads done; slots0-3 (dst) visible
    CPA_WAIT(0);
    __syncthreads();
    issue_chunk(sm_u32 + OFF_RING, 3, wbiP, w1P, tid); // buf1
    #pragma unroll
    for (int klc = 0; klc < 4; klc++)
        mma_step(smA, smRing + klc * 4096, klc, mi, ni, l16, C);
    sts_grp(pk, smA, 4, wid, l16);                     // drain dst grp1

    // B4: chunk3 done; buf0 reads done; slots4-7 (dst) visible
    CPA_WAIT(0);
    __syncthreads();
    issue_chunk(sm_u32 + OFF_RING, 4, wbiP, w1P, tid); // buf0
    #pragma unroll
    for (int klc = 0; klc < 4; klc++)
        mma_step(smA, smRing + 16384 + klc * 4096, 4 + klc, mi, ni, l16, C);

    // B5: chunk4 done; buf1 reads (chunk3) done -> safe to issue chunk5
    CPA_WAIT(0);
    __syncthreads();
    issue_chunk(sm_u32 + OFF_RING, 5, wbiP, w1P, tid); // buf1

    // ---- epilogue1 (half2): elu2(h2(C)+bias) -> A2 slots (ks2 = ni*4+s) ----
    #pragma unroll
    for (int s = 0; s < 4; s++) {
        const int hb = ni * 32 + s * 8 + t;
        const __half2 bb0 = sBbiH[hb];
        const __half2 bb1 = sBbiH[hb + 4];
        #pragma unroll
        for (int mtl = 0; mtl < 2; mtl++) {
            uint4 hi;
            hi.x = h2u(elu2(__hadd2(__floats2half2_rn(C[mtl][2*s][0],   C[mtl][2*s][1]),   bb0)));
            hi.y = h2u(elu2(__hadd2(__floats2half2_rn(C[mtl][2*s][2],   C[mtl][2*s][3]),   bb0)));
            hi.z = h2u(elu2(__hadd2(__floats2half2_rn(C[mtl][2*s+1][0], C[mtl][2*s+1][1]), bb1)));
            hi.w = h2u(elu2(__hadd2(__floats2half2_rn(C[mtl][2*s+1][2], C[mtl][2*s+1][3]), bb1)));
            const int mt2 = mi * 2 + mtl, ks2 = ni * 4 + s;
            *(uint4*)(smA + (mt2 * 8 + ks2) * 512 + l16) = hi;
        }
    }

    // ---- GEMM2: chunks 4,5 (W1), local ks 0..7; C reused ----
    #pragma unroll
    for (int m = 0; m < 2; m++)
        #pragma unroll
        for (int a = 0; a < 8; a++)
            #pragma unroll
            for (int b = 0; b < 4; b++) C[m][a][b] = 0.f;

    // B6: A2 slots visible (chunk4 already waited at B5)
    __syncthreads();
    #pragma unroll
    for (int klc = 0; klc < 4; klc++)
        mma_step(smA, smRing + klc * 4096, klc, mi, ni, l16, C);

    // B7: chunk5 visible
    CPA_WAIT(0);
    __syncthreads();
    #pragma unroll
    for (int klc = 0; klc < 4; klc++)
        mma_step(smA, smRing + 16384 + klc * 4096, 4 + klc, mi, ni, l16, C);

    // ---- epilogue2 (half2 elu, fp32 dot): ELU(C+b1).W2, quad reduce ----
    float r0[2] = {0.f, 0.f}, r1[2] = {0.f, 0.f};
    #pragma unroll
    for (int ntl = 0; ntl < 8; ntl++) {
        const int hb = ni * 32 + ntl * 4 + t;
        const __half2 b = sB1H[hb];
        const float2  w = sW2f2[hb];
        #pragma unroll
        for (int mtl = 0; mtl < 2; mtl++) {
            __half2 h01 = elu2(__hadd2(__floats2half2_rn(C[mtl][ntl][0], C[mtl][ntl][1]), b));
            __half2 h23 = elu2(__hadd2(__floats2half2_rn(C[mtl][ntl][2], C[mtl][ntl][3]), b));
            float2 f01 = __half22float2(h01);
            float2 f23 = __half22float2(h23);
            r0[mtl] += f01.x * w.x + f01.y * w.y;
            r1[mtl] += f23.x * w.x + f23.y * w.y;
        }
    }
    #pragma unroll
    for (int mtl = 0; mtl < 2; mtl++) {
        r0[mtl] += __shfl_xor_sync(0xffffffffu, r0[mtl], 1);
        r1[mtl] += __shfl_xor_sync(0xffffffffu, r1[mtl], 1);
        r0[mtl] += __shfl_xor_sync(0xffffffffu, r0[mtl], 2);
        r1[mtl] += __shfl_xor_sync(0xffffffffu, r1[mtl], 2);
        if (t == 0) {
            const int m = (mi * 2 + mtl) * 16 + g;
            sPart[ni * 64 + m]     = r0[mtl];
            sPart[ni * 64 + m + 8] = r1[mtl];
        }
    }
    // B8: sPart ready
    __syncthreads();
    if (tid < 64) {
        const int ge = base + tid;
        if (ge < E) {
            float s = sPart[tid] + sPart[64 + tid] + b2v;
            out[(size_t)type * E + ge] = 1.f / (1.f + __expf(-s));
        }
    }
}

extern "C" void kernel_launch(void* const* d_in, const int* in_sizes, int n_in,
                              void* d_out, int out_size) {
    (void)n_in; (void)out_size;
    const int E = in_sizes[2] / 2;
    pack_weights_kernel<<<96, 512>>>(
        (const float*)d_in[4], (const float*)d_in[6],
        (const float*)d_in[10], (const float*)d_in[12]);
    cudaFuncSetAttribute(edge_decoder_mma,
                         cudaFuncAttributeMaxDynamicSharedMemorySize, SMEM_TOTAL);
    dim3 grid((E + 63) / 64, 2);
    edge_decoder_mma<<<grid, NTH, SMEM_TOTAL>>>(
        (const float*)d_in[0],  (const float*)d_in[1],
        d_in[2], d_in[3],
        (const float*)d_in[5],  (const float*)d_in[7],
        (const float*)d_in[8],  (const float*)d_in[9],
        (const float*)d_in[11], (const float*)d_in[13],
        (const float*)d_in[14], (const float*)d_in[15],
        (float*)d_out, E);
}